// round 13
// baseline (speedup 1.0000x reference)
#include <cuda_runtime.h>
#include <cstdint>
#include <cstddef>

#define T_STEPS 2048
#define B_SZ    128
#define H_SZ    200
#define IN_SZ   88
#define OUT_SZ  88
#define G4H     800
#define CL_N    4        // CTAs per cluster
#define BG_SZ   4        // batches per cluster
#define U_PER   50       // hidden units per CTA

// lstm smem layout (words)
#define W_USTR   212                    // padded w row stride (bank-spread, f4-aligned)
#define W_WORDS  (4 * U_PER * W_USTR)   // 42400
#define HB_OFF   W_WORDS
#define HB_SRC   208                    // per-src block: [b:4][52]
#define HB_SZ    (CL_N * HB_SRC)        // 832 words per phase
#define ST_OFF   (HB_OFF + 2 * HB_SZ)   // 44064
#define ST_SZ    HB_SRC                 // staging: [b:4][52]
#define MB_OFF   (ST_OFF + 2 * ST_SZ)   // 44480 (8B aligned)
#define TX_BYTES (CL_N * HB_SRC * 4)    // 3328 B expected per phase
#define NTHR     256

// ---------------- scratch (static device globals) ---------------------------
__device__ float g_gx[(size_t)T_STEPS * G4H * B_SZ];   // [T][4H][B]
__device__ float g_y [(size_t)T_STEPS * B_SZ * H_SZ];  // [T][B][H]

__device__ __forceinline__ float sigm(float x) {
    return __frcp_rn(1.0f + __expf(-x));
}
__device__ __forceinline__ float tanh_f(float x) {
    float e = __expf(-2.0f * fabsf(x));
    float r = (1.0f - e) * __frcp_rn(1.0f + e);
    return copysignf(r, x);
}
__device__ __forceinline__ float2 unpack2(unsigned long long v) {
    float2 r;
    asm("mov.b64 {%0, %1}, %2;" : "=f"(r.x), "=f"(r.y) : "l"(v));
    return r;
}
#define FMA2(acc, a, b) \
    asm("fma.rn.f32x2 %0, %1, %2, %0;" : "+l"(acc) : "l"(a), "l"(b))

// ---------------- projection GEMM (unchanged — known good) -------------------
__global__ void proj_kernel(const float* __restrict__ A, const float* __restrict__ W,
                            const float* __restrict__ b1, const float* __restrict__ b2,
                            float* __restrict__ out, int K, int R, int mode)
{
    __shared__ float w_sm[16 * H_SZ];   // max K = 200

    int t   = blockIdx.y;
    int r0  = blockIdx.x * 16;
    int tid = threadIdx.x;
    int K4  = K >> 2;

    for (int i = tid; i < 16 * K4; i += 128) {
        int r = i / K4, kk = i % K4, rg = r0 + r;
        float4 v = make_float4(0.f, 0.f, 0.f, 0.f);
        if (rg < R) v = ((const float4*)(W + (size_t)rg * K))[kk];
        ((float4*)w_sm)[i] = v;
    }
    __syncthreads();

    int b = tid;
    unsigned long long acc[16];
#pragma unroll
    for (int r = 0; r < 16; r++) acc[r] = 0ULL;

    const ulonglong2* xrow = (const ulonglong2*)(A + ((size_t)t * B_SZ + b) * K);
#pragma unroll 2
    for (int kk = 0; kk < K4; kk++) {
        ulonglong2 xv = __ldg(xrow + kk);
#pragma unroll
        for (int r = 0; r < 16; r++) {
            ulonglong2 wv = *((const ulonglong2*)(w_sm + r * K) + kk);
            FMA2(acc[r], xv.x, wv.x);
            FMA2(acc[r], xv.y, wv.y);
        }
    }

    if (mode == 0) {
#pragma unroll
        for (int r = 0; r < 16; r++) {
            int rg = r0 + r;
            if (rg < R) {
                float2 p = unpack2(acc[r]);
                out[((size_t)t * R + rg) * B_SZ + b] =
                    p.x + p.y + b1[rg] + b2[rg];
            }
        }
    } else {
#pragma unroll
        for (int r = 0; r < 16; r++) {
            int rg = r0 + r;
            if (rg < R) {
                float2 p = unpack2(acc[r]);
                out[((size_t)t * B_SZ + b) * R + rg] = sigm(p.x + p.y + b1[rg]);
            }
        }
    }
}

// ---------------- persistent LSTM: 4-CTA cluster + bulk-copy pipeline --------
// Grid (4, 32), cluster (4,1,1). Thread (tid<200): b=tid&3, u=tid>>2.
// Per step: stage h locally (1 STS), __syncthreads, tid0 issues 4
// cp.async.bulk (smem->peer smem, 832B, tx-complete on peer mbar).
// Consumers: one local try_wait.parity per step. Two mbars (per buffer parity).
__device__ __forceinline__ void mbar_wait(unsigned addr, unsigned parity) {
    asm volatile(
        "{\n\t.reg .pred P;\n"
        "W%=:\n\t"
        "mbarrier.try_wait.parity.acquire.cta.shared::cta.b64 P, [%0], %1, 0x989680;\n\t"
        "@!P bra W%=;\n\t}"
        :: "r"(addr), "r"(parity) : "memory");
}

__global__ void __cluster_dims__(CL_N, 1, 1)
lstm_kernel(const float* __restrict__ gx,   // [T][4H][B]
            const float* __restrict__ whh,  // [4H][H]
            float* __restrict__ y,          // [T][B][H]
            float* __restrict__ hn, float* __restrict__ cn)
{
    extern __shared__ float sm[];
    float* w_sm = sm;                       // [g][u][src*52+kk], stride 212

    int tid = threadIdx.x;
    int jg  = blockIdx.x;                   // cluster rank
    int bg  = blockIdx.y;                   // batch-group 0..31

    // stage weights into padded layout (coalesced gmem reads)
    for (int i = tid; i < 4 * U_PER * H_SZ; i += NTHR) {
        int g = i / (U_PER * H_SZ), rem = i % (U_PER * H_SZ);
        int u = rem / H_SZ, k = rem % H_SZ;
        w_sm[(g * U_PER + u) * W_USTR + (k / 50) * 52 + (k % 50)] =
            whh[(size_t)(g * H_SZ + jg * U_PER + u) * H_SZ + k];
    }
    // zero h phase buffers + staging
    for (int i = tid; i < 2 * HB_SZ + 2 * ST_SZ; i += NTHR) sm[HB_OFF + i] = 0.f;

    unsigned smem_u32;
    {
        unsigned long long tmp;
        asm("cvta.to.shared.u64 %0, %1;" : "=l"(tmp) : "l"(sm));
        smem_u32 = (unsigned)tmp;
    }
    unsigned mb[2] = { smem_u32 + MB_OFF * 4u, smem_u32 + MB_OFF * 4u + 8u };

    if (tid == 0) {
        asm volatile("mbarrier.init.shared.b64 [%0], 1;" :: "r"(mb[0]) : "memory");
        asm volatile("mbarrier.init.shared.b64 [%0], 1;" :: "r"(mb[1]) : "memory");
        // arm both mbars' first phase (arrival 1/1; completion pends on tx)
        asm volatile("mbarrier.arrive.expect_tx.shared.b64 _, [%0], %1;"
                     :: "r"(mb[0]), "r"(TX_BYTES) : "memory");
        asm volatile("mbarrier.arrive.expect_tx.shared.b64 _, [%0], %1;"
                     :: "r"(mb[1]), "r"(TX_BYTES) : "memory");
    }
    __syncthreads();
    // all CTAs initialized before any remote copy can land
    asm volatile("barrier.cluster.arrive.aligned;" ::: "memory");
    asm volatile("barrier.cluster.wait.aligned;"   ::: "memory");

    bool active = tid < 200;
    int b = tid & 3, u = tid >> 2;
    int j = jg * U_PER + u, bglob = bg * BG_SZ + b;
    float c = 0.f;

    // tid0's remote copy targets: peer r's buf[phase][src=jg] + peer r's mbar
    unsigned rdst[2][CL_N], rmb[2][CL_N];
    if (tid == 0) {
#pragma unroll
        for (int p = 0; p < 2; p++) {
            unsigned dloc = smem_u32 + (HB_OFF + p * HB_SZ + jg * HB_SRC) * 4u;
#pragma unroll
            for (int r = 0; r < CL_N; r++) {
                asm("mapa.shared::cluster.u32 %0, %1, %2;"
                    : "=r"(rdst[p][r]) : "r"(dloc), "r"(r));
                asm("mapa.shared::cluster.u32 %0, %1, %2;"
                    : "=r"(rmb[p][r]) : "r"(mb[p]), "r"(r));
            }
        }
    }

    // preload gx for t = 0
    float gi = 0.f, gf = 0.f, gg = 0.f, go = 0.f;
    if (active) {
        size_t base = (size_t)j * B_SZ + bglob;
        gi = gx[base];
        gf = gx[base + 200 * B_SZ];
        gg = gx[base + 400 * B_SZ];
        go = gx[base + 600 * B_SZ];
    }

    int par[2] = {0, 0};

    for (int t = 0; t < T_STEPS; t++) {
        if (t > 0) {
            int m = t & 1;
            mbar_wait(mb[m], (unsigned)par[m]);
            par[m] ^= 1;
            if (tid == 0) {
                // re-arm this mbar for its next phase (provably before any
                // next-phase tx: senders depend on data we emit below)
                asm volatile("mbarrier.arrive.expect_tx.shared.b64 _, [%0], %1;"
                             :: "r"(mb[m]), "r"(TX_BYTES) : "memory");
            }
        }

        float h = 0.f;
        if (active) {
            const float* hb = sm + HB_OFF + (t & 1) * HB_SZ;
            unsigned long long ai = 0ULL, af = 0ULL, ag = 0ULL, ao = 0ULL;
#pragma unroll
            for (int src = 0; src < CL_N; src++) {
                const ulonglong2* h4 =
                    (const ulonglong2*)(hb + src * HB_SRC + b * 52);
                const ulonglong2* wi4 = (const ulonglong2*)
                    (w_sm + (0 * U_PER + u) * W_USTR + src * 52);
                const ulonglong2* wf4 = (const ulonglong2*)
                    (w_sm + (1 * U_PER + u) * W_USTR + src * 52);
                const ulonglong2* wg4 = (const ulonglong2*)
                    (w_sm + (2 * U_PER + u) * W_USTR + src * 52);
                const ulonglong2* wo4 = (const ulonglong2*)
                    (w_sm + (3 * U_PER + u) * W_USTR + src * 52);
#pragma unroll
                for (int kk = 0; kk < 12; kk++) {
                    ulonglong2 hv = h4[kk];
                    ulonglong2 w;
                    w = wi4[kk]; FMA2(ai, hv.x, w.x); FMA2(ai, hv.y, w.y);
                    w = wf4[kk]; FMA2(af, hv.x, w.x); FMA2(af, hv.y, w.y);
                    w = wg4[kk]; FMA2(ag, hv.x, w.x); FMA2(ag, hv.y, w.y);
                    w = wo4[kk]; FMA2(ao, hv.x, w.x); FMA2(ao, hv.y, w.y);
                }
                // tail: elements 48,49 of this 50-block
                unsigned long long ht = *(const unsigned long long*)
                    (hb + src * HB_SRC + b * 52 + 48);
                FMA2(ai, ht, *(const unsigned long long*)
                    (w_sm + (0 * U_PER + u) * W_USTR + src * 52 + 48));
                FMA2(af, ht, *(const unsigned long long*)
                    (w_sm + (1 * U_PER + u) * W_USTR + src * 52 + 48));
                FMA2(ag, ht, *(const unsigned long long*)
                    (w_sm + (2 * U_PER + u) * W_USTR + src * 52 + 48));
                FMA2(ao, ht, *(const unsigned long long*)
                    (w_sm + (3 * U_PER + u) * W_USTR + src * 52 + 48));
            }
            float2 pi = unpack2(ai), pf = unpack2(af);
            float2 pg = unpack2(ag), po = unpack2(ao);
            float I = sigm(pi.x + pi.y + gi);
            float F = sigm(pf.x + pf.y + gf);
            float G = tanh_f(pg.x + pg.y + gg);
            float O = sigm(po.x + po.y + go);
            c = F * c + I * G;
            h = O * tanh_f(c);

            // stage h locally for the bulk copy
            sm[ST_OFF + ((t + 1) & 1) * ST_SZ + b * 52 + u] = h;
        }

        __syncthreads();   // staging complete across CTA

        if (tid == 0 && t + 1 < T_STEPS) {
            int p = (t + 1) & 1;
            unsigned src_addr = smem_u32 + (ST_OFF + p * ST_SZ) * 4u;
            asm volatile("fence.proxy.async.shared::cta;" ::: "memory");
#pragma unroll
            for (int r = 0; r < CL_N; r++) {
                asm volatile(
                    "cp.async.bulk.shared::cluster.shared::cta."
                    "mbarrier::complete_tx::bytes [%0], [%1], %2, [%3];"
                    :: "r"(rdst[p][r]), "r"(src_addr),
                       "r"((unsigned)(HB_SRC * 4)), "r"(rmb[p][r])
                    : "memory");
            }
        }

        // outputs + next-step gx prefetch overlap copy flight
        float ni = 0.f, nf = 0.f, ng = 0.f, no = 0.f;
        if (active) {
            y[((size_t)t * B_SZ + bglob) * H_SZ + j] = h;
            if (t + 1 < T_STEPS) {
                size_t base = ((size_t)(t + 1) * G4H + j) * B_SZ + bglob;
                ni = gx[base];
                nf = gx[base + 200 * B_SZ];
                ng = gx[base + 400 * B_SZ];
                no = gx[base + 600 * B_SZ];
            } else {
                hn[bglob * H_SZ + j] = h;
                cn[bglob * H_SZ + j] = c;
            }
        }

        gi = ni; gf = nf; gg = ng; go = no;
    }

    // keep smem/mbars alive until all cluster traffic drained
    asm volatile("barrier.cluster.arrive.aligned;" ::: "memory");
    asm volatile("barrier.cluster.wait.aligned;"   ::: "memory");
}

// ---------------- launch ----------------------------------------------------
extern "C" void kernel_launch(void* const* d_in, const int* in_sizes, int n_in,
                              void* d_out, int out_size)
{
    const float* x     = (const float*)d_in[0];
    const float* w_ih0 = (const float*)d_in[1];
    const float* w_hh0 = (const float*)d_in[2];
    const float* b_ih0 = (const float*)d_in[3];
    const float* b_hh0 = (const float*)d_in[4];
    const float* w_ih1 = (const float*)d_in[5];
    const float* w_hh1 = (const float*)d_in[6];
    const float* b_ih1 = (const float*)d_in[7];
    const float* b_hh1 = (const float*)d_in[8];
    const float* w_fc  = (const float*)d_in[9];
    const float* b_fc  = (const float*)d_in[10];

    float* out = (float*)d_out;
    float* hn  = out + (size_t)T_STEPS * B_SZ * OUT_SZ;   // [2][B][H]
    float* cn  = hn + 2 * B_SZ * H_SZ;

    void *gx_p, *y_p;
    cudaGetSymbolAddress(&gx_p, g_gx);
    cudaGetSymbolAddress(&y_p,  g_y);
    float* gxb = (float*)gx_p;
    float* yb  = (float*)y_p;

    const int lstm_smem = (MB_OFF + 4) * 4;               // ~173.8 KB
    cudaFuncSetAttribute(lstm_kernel,
                         cudaFuncAttributeMaxDynamicSharedMemorySize, lstm_smem);

    dim3 lstm_grid(CL_N, B_SZ / BG_SZ);                   // (4, 32)

    // ----- layer 0 -----
    proj_kernel<<<dim3(50, T_STEPS), 128>>>(x, w_ih0, b_ih0, b_hh0,
                                            gxb, IN_SZ, G4H, 0);
    lstm_kernel<<<lstm_grid, NTHR, lstm_smem>>>(gxb, w_hh0, yb, hn, cn);

    // ----- layer 1 -----
    proj_kernel<<<dim3(50, T_STEPS), 128>>>(yb, w_ih1, b_ih1, b_hh1,
                                            gxb, H_SZ, G4H, 0);
    lstm_kernel<<<lstm_grid, NTHR, lstm_smem>>>(gxb, w_hh1, yb,
                                                hn + B_SZ * H_SZ,
                                                cn + B_SZ * H_SZ);

    // ----- FC head -----
    proj_kernel<<<dim3(6, T_STEPS), 128>>>(yb, w_fc, b_fc, nullptr,
                                           out, H_SZ, OUT_SZ, 1);
}

// round 14
// speedup vs baseline: 1.4881x; 1.4881x over previous
#include <cuda_runtime.h>
#include <cstdint>
#include <cstddef>

#define T_STEPS 2048
#define B_SZ    128
#define H_SZ    200
#define IN_SZ   88
#define OUT_SZ  88
#define G4H     800
#define CL_N    4        // CTAs per cluster
#define BG_SZ   4        // batches per cluster (batch-group)
#define U_PER   50       // hidden units per CTA

// ---------------- scratch (static device globals) ---------------------------
__device__ float g_gx[(size_t)T_STEPS * G4H * B_SZ];   // [T][4H][B]
__device__ float g_y [(size_t)T_STEPS * B_SZ * H_SZ];  // [T][B][H]

__device__ __forceinline__ float sigm(float x) {
    return __frcp_rn(1.0f + __expf(-x));
}
__device__ __forceinline__ float tanh_f(float x) {
    float e = __expf(-2.0f * fabsf(x));
    float r = (1.0f - e) * __frcp_rn(1.0f + e);
    return copysignf(r, x);
}
__device__ __forceinline__ float2 unpack2(unsigned long long v) {
    float2 r;
    asm("mov.b64 {%0, %1}, %2;" : "=f"(r.x), "=f"(r.y) : "l"(v));
    return r;
}
#define FMA2(acc, a, b) \
    asm("fma.rn.f32x2 %0, %1, %2, %0;" : "+l"(acc) : "l"(a), "l"(b))

// ---------------- projection GEMM (unchanged — known good) -------------------
__global__ void proj_kernel(const float* __restrict__ A, const float* __restrict__ W,
                            const float* __restrict__ b1, const float* __restrict__ b2,
                            float* __restrict__ out, int K, int R, int mode)
{
    __shared__ float w_sm[16 * H_SZ];   // max K = 200

    int t   = blockIdx.y;
    int r0  = blockIdx.x * 16;
    int tid = threadIdx.x;
    int K4  = K >> 2;

    for (int i = tid; i < 16 * K4; i += 128) {
        int r = i / K4, kk = i % K4, rg = r0 + r;
        float4 v = make_float4(0.f, 0.f, 0.f, 0.f);
        if (rg < R) v = ((const float4*)(W + (size_t)rg * K))[kk];
        ((float4*)w_sm)[i] = v;
    }
    __syncthreads();

    int b = tid;
    unsigned long long acc[16];
#pragma unroll
    for (int r = 0; r < 16; r++) acc[r] = 0ULL;

    const ulonglong2* xrow = (const ulonglong2*)(A + ((size_t)t * B_SZ + b) * K);
#pragma unroll 2
    for (int kk = 0; kk < K4; kk++) {
        ulonglong2 xv = __ldg(xrow + kk);
#pragma unroll
        for (int r = 0; r < 16; r++) {
            ulonglong2 wv = *((const ulonglong2*)(w_sm + r * K) + kk);
            FMA2(acc[r], xv.x, wv.x);
            FMA2(acc[r], xv.y, wv.y);
        }
    }

    if (mode == 0) {
#pragma unroll
        for (int r = 0; r < 16; r++) {
            int rg = r0 + r;
            if (rg < R) {
                float2 p = unpack2(acc[r]);
                out[((size_t)t * R + rg) * B_SZ + b] =
                    p.x + p.y + b1[rg] + b2[rg];
            }
        }
    } else {
#pragma unroll
        for (int r = 0; r < 16; r++) {
            int rg = r0 + r;
            if (rg < R) {
                float2 p = unpack2(acc[r]);
                out[((size_t)t * B_SZ + b) * R + rg] = sigm(p.x + p.y + b1[rg]);
            }
        }
    }
}

// ---------------- persistent LSTM recurrence: 4-CTA cluster ------------------
// Identical to the 17.9ms R8 kernel EXCEPT the w_sm unit stride is padded
// 200 -> 204 words: u*204 mod 32 = u*12 mod 32 gives the 8 u-groups per warp
// the bank-chunk offsets {0,12,24,4,16,28,8,20} — a perfect 32-bank partition,
// so every w LDS.128 is 1 wavefront instead of 2.
#define W_USTR   204
#define W_WORDS  (4 * U_PER * W_USTR)           // 40800
#define HS_OFF   W_WORDS
#define HS_BUF   (BG_SZ * 204)                  // 816
__global__ void __cluster_dims__(CL_N, 1, 1)
lstm_kernel(const float* __restrict__ gx,   // [T][4H][B]
            const float* __restrict__ whh,  // [4H][H]
            float* __restrict__ y,          // [T][B][H]
            float* __restrict__ hn, float* __restrict__ cn)
{
    extern __shared__ float sm[];
    float* w_sm = sm;                       // [g][u] stride 204

    int tid = threadIdx.x;
    int jg  = blockIdx.x;                   // cluster rank
    int bg  = blockIdx.y;                   // batch-group 0..31

    // stage this CTA's weight slice into padded layout (coalesced over k)
    for (int i = tid; i < 4 * U_PER * H_SZ; i += 256) {
        int g = i / (U_PER * H_SZ), rem = i % (U_PER * H_SZ);
        int u = rem / H_SZ, k = rem % H_SZ;
        w_sm[(g * U_PER + u) * W_USTR + k] =
            whh[(size_t)(g * H_SZ + jg * U_PER + u) * H_SZ + k];
    }
    // zero h double-buffer
    for (int i = tid; i < 2 * HS_BUF; i += 256) sm[HS_OFF + i] = 0.f;
    __syncthreads();
    // all CTAs initialized before any remote store can land
    asm volatile("barrier.cluster.arrive.aligned;" ::: "memory");
    asm volatile("barrier.cluster.wait.aligned;"   ::: "memory");

    unsigned smem_u32;
    {
        unsigned long long tmp;
        asm("cvta.to.shared.u64 %0, %1;" : "=l"(tmp) : "l"(sm));
        smem_u32 = (unsigned)tmp;
    }

    bool active = tid < 200;
    int b = tid & 3, u = tid >> 2;
    int j = jg * U_PER + u, bglob = bg * BG_SZ + b;
    float c = 0.f;

    // precomputed remote h slots for this thread (one per rank)
    unsigned rh[CL_N];
    {
        unsigned hloc = smem_u32 + (HS_OFF + b * 204 + j) * 4u;
#pragma unroll
        for (int r = 0; r < CL_N; r++)
            asm("mapa.shared::cluster.u32 %0, %1, %2;"
                : "=r"(rh[r]) : "r"(hloc), "r"(r));
    }

    const ulonglong2* wi2 = (const ulonglong2*)(w_sm + (0 * U_PER + u) * W_USTR);
    const ulonglong2* wf2 = (const ulonglong2*)(w_sm + (1 * U_PER + u) * W_USTR);
    const ulonglong2* wg2 = (const ulonglong2*)(w_sm + (2 * U_PER + u) * W_USTR);
    const ulonglong2* wo2 = (const ulonglong2*)(w_sm + (3 * U_PER + u) * W_USTR);

    // preload gx for t = 0
    float gi = 0.f, gf = 0.f, gg = 0.f, go = 0.f;
    if (active) {
        size_t base = (size_t)j * B_SZ + bglob;
        gi = gx[base];
        gf = gx[base + 200 * B_SZ];
        gg = gx[base + 400 * B_SZ];
        go = gx[base + 600 * B_SZ];
    }

    for (int t = 0; t < T_STEPS; t++) {
        float h = 0.f;
        if (active) {
            const ulonglong2* h2 =
                (const ulonglong2*)(sm + HS_OFF + (t & 1) * HS_BUF + b * 204);
            unsigned long long ai = 0ULL, af = 0ULL, ag = 0ULL, ao = 0ULL;
#pragma unroll
            for (int kk = 0; kk < 50; kk++) {
                ulonglong2 hv = h2[kk];
                ulonglong2 w;
                w = wi2[kk]; FMA2(ai, hv.x, w.x); FMA2(ai, hv.y, w.y);
                w = wf2[kk]; FMA2(af, hv.x, w.x); FMA2(af, hv.y, w.y);
                w = wg2[kk]; FMA2(ag, hv.x, w.x); FMA2(ag, hv.y, w.y);
                w = wo2[kk]; FMA2(ao, hv.x, w.x); FMA2(ao, hv.y, w.y);
            }
            float2 pi = unpack2(ai), pf = unpack2(af);
            float2 pg = unpack2(ag), po = unpack2(ao);
            float I = sigm(pi.x + pi.y + gi);
            float F = sigm(pf.x + pf.y + gf);
            float G = tanh_f(pg.x + pg.y + gg);
            float O = sigm(po.x + po.y + go);
            c = F * c + I * G;
            h = O * tanh_f(c);

            // push h into every cluster CTA's next-step buffer
            unsigned bofs = (unsigned)(((t + 1) & 1) * (HS_BUF * 4));
#pragma unroll
            for (int r = 0; r < CL_N; r++) {
                asm volatile("st.shared::cluster.f32 [%0], %1;"
                             :: "r"(rh[r] + bofs), "f"(h) : "memory");
            }
        }

        // split barrier: arrive (release covers DSMEM stores), overlap the
        // gmem output store + next-step gx prefetch with peer skew, then wait.
        asm volatile("barrier.cluster.arrive.aligned;" ::: "memory");

        float ni = 0.f, nf = 0.f, ng = 0.f, no = 0.f;
        if (active) {
            y[((size_t)t * B_SZ + bglob) * H_SZ + j] = h;
            if (t + 1 < T_STEPS) {
                size_t base = ((size_t)(t + 1) * G4H + j) * B_SZ + bglob;
                ni = gx[base];
                nf = gx[base + 200 * B_SZ];
                ng = gx[base + 400 * B_SZ];
                no = gx[base + 600 * B_SZ];
            } else {
                hn[bglob * H_SZ + j] = h;
                cn[bglob * H_SZ + j] = c;
            }
        }

        asm volatile("barrier.cluster.wait.aligned;" ::: "memory");

        gi = ni; gf = nf; gg = ng; go = no;
    }
}

// ---------------- launch ----------------------------------------------------
extern "C" void kernel_launch(void* const* d_in, const int* in_sizes, int n_in,
                              void* d_out, int out_size)
{
    const float* x     = (const float*)d_in[0];
    const float* w_ih0 = (const float*)d_in[1];
    const float* w_hh0 = (const float*)d_in[2];
    const float* b_ih0 = (const float*)d_in[3];
    const float* b_hh0 = (const float*)d_in[4];
    const float* w_ih1 = (const float*)d_in[5];
    const float* w_hh1 = (const float*)d_in[6];
    const float* b_ih1 = (const float*)d_in[7];
    const float* b_hh1 = (const float*)d_in[8];
    const float* w_fc  = (const float*)d_in[9];
    const float* b_fc  = (const float*)d_in[10];

    float* out = (float*)d_out;
    float* hn  = out + (size_t)T_STEPS * B_SZ * OUT_SZ;   // [2][B][H]
    float* cn  = hn + 2 * B_SZ * H_SZ;

    void *gx_p, *y_p;
    cudaGetSymbolAddress(&gx_p, g_gx);
    cudaGetSymbolAddress(&y_p,  g_y);
    float* gxb = (float*)gx_p;
    float* yb  = (float*)y_p;

    const int lstm_smem = (W_WORDS + 2 * HS_BUF) * 4;     // ~169.7 KB
    cudaFuncSetAttribute(lstm_kernel,
                         cudaFuncAttributeMaxDynamicSharedMemorySize, lstm_smem);

    dim3 lstm_grid(CL_N, B_SZ / BG_SZ);                   // (4, 32)

    // ----- layer 0 -----
    proj_kernel<<<dim3(50, T_STEPS), 128>>>(x, w_ih0, b_ih0, b_hh0,
                                            gxb, IN_SZ, G4H, 0);
    lstm_kernel<<<lstm_grid, 256, lstm_smem>>>(gxb, w_hh0, yb, hn, cn);

    // ----- layer 1 -----
    proj_kernel<<<dim3(50, T_STEPS), 128>>>(yb, w_ih1, b_ih1, b_hh1,
                                            gxb, H_SZ, G4H, 0);
    lstm_kernel<<<lstm_grid, 256, lstm_smem>>>(gxb, w_hh1, yb,
                                               hn + B_SZ * H_SZ,
                                               cn + B_SZ * H_SZ);

    // ----- FC head -----
    proj_kernel<<<dim3(6, T_STEPS), 128>>>(yb, w_fc, b_fc, nullptr,
                                           out, H_SZ, OUT_SZ, 1);
}